// round 1
// baseline (speedup 1.0000x reference)
#include <cuda_runtime.h>

// InvertAffine: input (B, 3, 4) fp32 affine "shift" matrices.
// padded = [[I3 + A, t], [0 0 0 1]]; inverse top-3-rows = [R, -R t], R = (I3+A)^-1.
// Closed-form 3x3 adjugate inverse per matrix. Pure HBM-streaming kernel:
// 48 B in + 48 B out per matrix, one thread per matrix, float4 ld/st.

__global__ void __launch_bounds__(256) invert_affine_kernel(
    const float4* __restrict__ in, float4* __restrict__ out, int b)
{
    int i = blockIdx.x * blockDim.x + threadIdx.x;
    if (i >= b) return;

    const float4 r0 = in[3 * i + 0];
    const float4 r1 = in[3 * i + 1];
    const float4 r2 = in[3 * i + 2];

    // M = I3 + A (top-left 3x3), t = last column
    const float m00 = r0.x + 1.0f, m01 = r0.y,        m02 = r0.z,        t0 = r0.w;
    const float m10 = r1.x,        m11 = r1.y + 1.0f, m12 = r1.z,        t1 = r1.w;
    const float m20 = r2.x,        m21 = r2.y,        m22 = r2.z + 1.0f, t2 = r2.w;

    // Cofactors (first column of adjugate) + determinant
    const float c00 = m11 * m22 - m12 * m21;
    const float c10 = m12 * m20 - m10 * m22;
    const float c20 = m10 * m21 - m11 * m20;
    const float det = m00 * c00 + m01 * c10 + m02 * c20;
    const float rdet = 1.0f / det;

    // R = adj(M)^T / det
    const float i00 = c00 * rdet;
    const float i01 = (m02 * m21 - m01 * m22) * rdet;
    const float i02 = (m01 * m12 - m02 * m11) * rdet;
    const float i10 = c10 * rdet;
    const float i11 = (m00 * m22 - m02 * m20) * rdet;
    const float i12 = (m02 * m10 - m00 * m12) * rdet;
    const float i20 = c20 * rdet;
    const float i21 = (m01 * m20 - m00 * m21) * rdet;
    const float i22 = (m00 * m11 - m01 * m10) * rdet;

    // -R * t
    const float o0 = -(i00 * t0 + i01 * t1 + i02 * t2);
    const float o1 = -(i10 * t0 + i11 * t1 + i12 * t2);
    const float o2 = -(i20 * t0 + i21 * t1 + i22 * t2);

    out[3 * i + 0] = make_float4(i00, i01, i02, o0);
    out[3 * i + 1] = make_float4(i10, i11, i12, o1);
    out[3 * i + 2] = make_float4(i20, i21, i22, o2);
}

extern "C" void kernel_launch(void* const* d_in, const int* in_sizes, int n_in,
                              void* d_out, int out_size)
{
    const float4* in = (const float4*)d_in[0];
    float4* out = (float4*)d_out;
    const int b = in_sizes[0] / 12;  // (B, 3, 4) fp32 -> 12 elements per matrix

    const int threads = 256;
    const int blocks = (b + threads - 1) / threads;
    invert_affine_kernel<<<blocks, threads>>>(in, out, b);
}

// round 2
// speedup vs baseline: 1.0263x; 1.0263x over previous
#include <cuda_runtime.h>

// InvertAffine: (B, 3, 4) fp32 affine shift matrices.
// inverse top-3-rows = [R, -R t], R = (I3+A)^-1 via closed-form 3x3 adjugate.
//
// Round-2 change: shared-memory staging so ALL global traffic is fully
// coalesced (lane stride 16B), eliminating the 3x L1tex wavefront
// amplification of the per-thread stride-48B pattern. Smem access at
// stride 12 floats is bank-conflict-free for LDS.128/STS.128.

__global__ void __launch_bounds__(256, 8) invert_affine_kernel(
    const float4* __restrict__ in, float4* __restrict__ out, int b)
{
    __shared__ float4 s[768];  // 256 matrices * 3 float4 = 12 KB

    const int t = threadIdx.x;
    const int mbase = blockIdx.x * 256;          // first matrix of this block
    const long long fbase = (long long)mbase * 3; // first float4 of this block
    const int nmat = min(256, b - mbase);
    const int nf4 = nmat * 3;

    // Coalesced gmem -> smem (3 x LDG.128, 4 lines per warp request)
#pragma unroll
    for (int k = 0; k < 3; k++) {
        const int idx = t + k * 256;
        if (idx < nf4) s[idx] = in[fbase + idx];
    }
    __syncthreads();

    const bool active = t < nmat;
    float4 a0, a1, a2;
    if (active) {
        a0 = s[3 * t + 0];
        a1 = s[3 * t + 1];
        a2 = s[3 * t + 2];
    }

    // M = I3 + A, t = last column
    const float m00 = a0.x + 1.0f, m01 = a0.y,        m02 = a0.z,        t0 = a0.w;
    const float m10 = a1.x,        m11 = a1.y + 1.0f, m12 = a1.z,        t1 = a1.w;
    const float m20 = a2.x,        m21 = a2.y,        m22 = a2.z + 1.0f, t2 = a2.w;

    // Cofactors (first column of adjugate) + determinant
    const float c00 = m11 * m22 - m12 * m21;
    const float c10 = m12 * m20 - m10 * m22;
    const float c20 = m10 * m21 - m11 * m20;
    const float det = m00 * c00 + m01 * c10 + m02 * c20;
    const float rdet = 1.0f / det;

    // R = adj(M)^T / det
    const float i00 = c00 * rdet;
    const float i01 = (m02 * m21 - m01 * m22) * rdet;
    const float i02 = (m01 * m12 - m02 * m11) * rdet;
    const float i10 = c10 * rdet;
    const float i11 = (m00 * m22 - m02 * m20) * rdet;
    const float i12 = (m02 * m10 - m00 * m12) * rdet;
    const float i20 = c20 * rdet;
    const float i21 = (m01 * m20 - m00 * m21) * rdet;
    const float i22 = (m00 * m11 - m01 * m10) * rdet;

    // -R * t
    const float o0 = -(i00 * t0 + i01 * t1 + i02 * t2);
    const float o1 = -(i10 * t0 + i11 * t1 + i12 * t2);
    const float o2 = -(i20 * t0 + i21 * t1 + i22 * t2);

    __syncthreads();  // all smem reads done before overwrite
    if (active) {
        s[3 * t + 0] = make_float4(i00, i01, i02, o0);
        s[3 * t + 1] = make_float4(i10, i11, i12, o1);
        s[3 * t + 2] = make_float4(i20, i21, i22, o2);
    }
    __syncthreads();

    // Coalesced smem -> gmem (3 x STG.128)
#pragma unroll
    for (int k = 0; k < 3; k++) {
        const int idx = t + k * 256;
        if (idx < nf4) out[fbase + idx] = s[idx];
    }
}

extern "C" void kernel_launch(void* const* d_in, const int* in_sizes, int n_in,
                              void* d_out, int out_size)
{
    const float4* in = (const float4*)d_in[0];
    float4* out = (float4*)d_out;
    const int b = in_sizes[0] / 12;  // (B, 3, 4) fp32 -> 12 elements per matrix

    const int threads = 256;
    const int blocks = (b + threads - 1) / threads;
    invert_affine_kernel<<<blocks, threads>>>(in, out, b);
}